// round 1
// baseline (speedup 1.0000x reference)
#include <cuda_runtime.h>
#include <cstddef>

#define TT   8192
#define DIN  4096
#define DOUT 4096
#define NE   8
#define RNK  16
#define ERD  128          // NE * RNK
#define SCAL 2.0f         // LORA_ALPHA / RANK

// Scratch (allocation-free rule: __device__ globals)
__device__ float g_w[TT * NE];        // dense combine weights (zeros for unselected)
__device__ float g_G[TT * ERD];       // SCALING * w[t,e] * h[t,e,r]
__device__ float g_Bt[ERD * DOUT];    // Bt[j, o] = B[e, o, r], j = e*16+r

// ---------------------------------------------------------------------------
// Router: logits = x @ W_router^T, top-2, softmax -> dense g_w[t, 8]
// one warp per token
// ---------------------------------------------------------------------------
__global__ void router_kernel(const float* __restrict__ x,
                              const float* __restrict__ Wr) {
    int gw   = (blockIdx.x * blockDim.x + threadIdx.x) >> 5;
    int lane = threadIdx.x & 31;
    if (gw >= TT) return;
    const float* xr = x + (size_t)gw * DIN;
    float acc[NE];
#pragma unroll
    for (int e = 0; e < NE; e++) acc[e] = 0.f;
    for (int d = lane * 4; d < DIN; d += 128) {
        float4 xv = *(const float4*)(xr + d);
#pragma unroll
        for (int e = 0; e < NE; e++) {
            float4 wv = *(const float4*)(Wr + e * DIN + d);
            acc[e] += xv.x * wv.x + xv.y * wv.y + xv.z * wv.z + xv.w * wv.w;
        }
    }
#pragma unroll
    for (int e = 0; e < NE; e++) {
#pragma unroll
        for (int off = 16; off > 0; off >>= 1)
            acc[e] += __shfl_xor_sync(0xffffffffu, acc[e], off);
    }
    if (lane == 0) {
        int i0 = 0; float v0 = acc[0];
#pragma unroll
        for (int e = 1; e < NE; e++) if (acc[e] > v0) { v0 = acc[e]; i0 = e; }
        int i1 = -1; float v1 = -3.4e38f;
#pragma unroll
        for (int e = 0; e < NE; e++) if (e != i0 && acc[e] > v1) { v1 = acc[e]; i1 = e; }
        float e1  = expf(v1 - v0);
        float inv = 1.0f / (1.0f + e1);
#pragma unroll
        for (int e = 0; e < NE; e++) g_w[gw * NE + e] = 0.f;
        g_w[gw * NE + i0] = inv;
        g_w[gw * NE + i1] = e1 * inv;
    }
}

// ---------------------------------------------------------------------------
// Bt[j, o] = B[e, o, r]  (B is [E, DOUT, R] row-major), j = e*16 + r
// ---------------------------------------------------------------------------
__global__ void bt_kernel(const float* __restrict__ B) {
    int idx = blockIdx.x * 256 + threadIdx.x;
    if (idx >= ERD * DOUT) return;
    int j = idx / DOUT;
    int o = idx - j * DOUT;
    int e = j >> 4, r = j & 15;
    g_Bt[idx] = B[((size_t)e * DOUT + o) * RNK + r];
}

// ---------------------------------------------------------------------------
// LoRA down:  g_G[t, j] = SCAL * w[t, j>>4] * (x[t,:] . A[j,:])
// GEMM M=8192, N=128, K=4096.  BM=32, BN=128, BK=16, 256 thr, 2x8 per thread
// ---------------------------------------------------------------------------
__global__ __launch_bounds__(256)
void lora_down_kernel(const float* __restrict__ x, const float* __restrict__ A) {
    __shared__ float Xs[16][32];
    __shared__ float As[16][ERD];
    int tid  = threadIdx.x;
    int tx   = tid & 15;   // 8-col group
    int ty   = tid >> 4;   // 2-row group
    int row0 = blockIdx.x * 32;

    float acc[2][8];
#pragma unroll
    for (int i = 0; i < 2; i++)
#pragma unroll
        for (int j = 0; j < 8; j++) acc[i][j] = 0.f;

    for (int k0 = 0; k0 < DIN; k0 += 16) {
        __syncthreads();
        if (tid < 128) {
            int r  = tid >> 2;
            int ds = (tid & 3) << 2;
            float4 v = *(const float4*)(x + (size_t)(row0 + r) * DIN + k0 + ds);
            Xs[ds + 0][r] = v.x; Xs[ds + 1][r] = v.y;
            Xs[ds + 2][r] = v.z; Xs[ds + 3][r] = v.w;
        }
#pragma unroll
        for (int l = 0; l < 2; l++) {
            int idx = tid + l * 256;
            int j   = idx >> 2;
            int ds  = (idx & 3) << 2;
            float4 v = *(const float4*)(A + (size_t)j * DIN + k0 + ds);
            As[ds + 0][j] = v.x; As[ds + 1][j] = v.y;
            As[ds + 2][j] = v.z; As[ds + 3][j] = v.w;
        }
        __syncthreads();
#pragma unroll
        for (int d = 0; d < 16; d++) {
            float a0 = Xs[d][ty * 2 + 0];
            float a1 = Xs[d][ty * 2 + 1];
            float b[8];
            *(float4*)(b)     = *(const float4*)&As[d][tx * 8];
            *(float4*)(b + 4) = *(const float4*)&As[d][tx * 8 + 4];
#pragma unroll
            for (int j = 0; j < 8; j++) {
                acc[0][j] = fmaf(a0, b[j], acc[0][j]);
                acc[1][j] = fmaf(a1, b[j], acc[1][j]);
            }
        }
    }

    int e = tx >> 1;   // 8 cols of this thread lie inside one expert's 16-block
#pragma unroll
    for (int i = 0; i < 2; i++) {
        int t = row0 + ty * 2 + i;
        float wsc = g_w[t * NE + e] * SCAL;
        float4 v0, v1;
        v0.x = acc[i][0] * wsc; v0.y = acc[i][1] * wsc;
        v0.z = acc[i][2] * wsc; v0.w = acc[i][3] * wsc;
        v1.x = acc[i][4] * wsc; v1.y = acc[i][5] * wsc;
        v1.z = acc[i][6] * wsc; v1.w = acc[i][7] * wsc;
        *(float4*)(g_G + (size_t)t * ERD + tx * 8)     = v0;
        *(float4*)(g_G + (size_t)t * ERD + tx * 8 + 4) = v1;
    }
}

// ---------------------------------------------------------------------------
// Fused main GEMM: out = x @ W^T  +  G @ Bt  +  bias
// BM=BN=128, BK=8, 256 threads, 8x8 per thread, double-buffered smem.
// ---------------------------------------------------------------------------
__device__ __forceinline__ void mm8(const float (*Xs)[128], const float (*Ws)[128],
                                    int ty8, int tx8, float acc[8][8]) {
#pragma unroll
    for (int kk = 0; kk < 8; kk++) {
        float a[8], b[8];
        *(float4*)(a)     = *(const float4*)&Xs[kk][ty8];
        *(float4*)(a + 4) = *(const float4*)&Xs[kk][ty8 + 4];
        *(float4*)(b)     = *(const float4*)&Ws[kk][tx8];
        *(float4*)(b + 4) = *(const float4*)&Ws[kk][tx8 + 4];
#pragma unroll
        for (int i = 0; i < 8; i++)
#pragma unroll
            for (int j = 0; j < 8; j++)
                acc[i][j] = fmaf(a[i], b[j], acc[i][j]);
    }
}

__global__ __launch_bounds__(256, 2)
void fused_gemm_kernel(const float* __restrict__ X, const float* __restrict__ W,
                       const float* __restrict__ bias, float* __restrict__ out) {
    __shared__ float Xs[2][8][128];
    __shared__ float Ws[2][8][128];
    int tid  = threadIdx.x;
    int tx8  = (tid & 15) << 3;
    int ty8  = (tid >> 4) << 3;
    int row0 = blockIdx.y << 7;
    int col0 = blockIdx.x << 7;

    int lr = tid >> 1;
    int lc = (tid & 1) << 2;
    const float* Xp = X + (size_t)(row0 + lr) * DIN + lc;
    const float* Wp = W + (size_t)(col0 + lr) * DIN + lc;

    float acc[8][8];
#pragma unroll
    for (int i = 0; i < 8; i++)
#pragma unroll
        for (int j = 0; j < 8; j++) acc[i][j] = 0.f;

    // prologue: tile 0 -> buf 0
    {
        float4 xv = *(const float4*)Xp;
        float4 wv = *(const float4*)Wp;
        Xs[0][lc + 0][lr] = xv.x; Xs[0][lc + 1][lr] = xv.y;
        Xs[0][lc + 2][lr] = xv.z; Xs[0][lc + 3][lr] = xv.w;
        Ws[0][lc + 0][lr] = wv.x; Ws[0][lc + 1][lr] = wv.y;
        Ws[0][lc + 2][lr] = wv.z; Ws[0][lc + 3][lr] = wv.w;
    }
    __syncthreads();

    int buf = 0;
    for (int kt = 1; kt < DIN / 8; kt++) {
        float4 xv = *(const float4*)(Xp + kt * 8);
        float4 wv = *(const float4*)(Wp + kt * 8);
        mm8(Xs[buf], Ws[buf], ty8, tx8, acc);
        buf ^= 1;
        Xs[buf][lc + 0][lr] = xv.x; Xs[buf][lc + 1][lr] = xv.y;
        Xs[buf][lc + 2][lr] = xv.z; Xs[buf][lc + 3][lr] = xv.w;
        Ws[buf][lc + 0][lr] = wv.x; Ws[buf][lc + 1][lr] = wv.y;
        Ws[buf][lc + 2][lr] = wv.z; Ws[buf][lc + 3][lr] = wv.w;
        __syncthreads();
    }
    mm8(Xs[buf], Ws[buf], ty8, tx8, acc);

    // phase 2: LoRA-up augmentation, K2 = 128 over (G, Bt)
    const float* Gp = g_G + (size_t)(row0 + lr) * ERD + lc;
    int bj = tid >> 5;          // 0..7   (k-row of Bt tile)
    int bo = (tid & 31) << 2;   // 0..124 (col chunk)
    for (int kt2 = 0; kt2 < ERD / 8; kt2++) {
        __syncthreads();   // protect previous reads of buffer 0
        float4 gv = *(const float4*)(Gp + kt2 * 8);
        Xs[0][lc + 0][lr] = gv.x; Xs[0][lc + 1][lr] = gv.y;
        Xs[0][lc + 2][lr] = gv.z; Xs[0][lc + 3][lr] = gv.w;
        float4 bv = *(const float4*)(g_Bt + (size_t)(kt2 * 8 + bj) * DOUT + col0 + bo);
        *(float4*)&Ws[0][bj][bo] = bv;   // Bt tile already [k][n]
        __syncthreads();
        mm8(Xs[0], Ws[0], ty8, tx8, acc);
    }

    // epilogue: + bias, vectorized stores
    float4 bb0 = *(const float4*)(bias + col0 + tx8);
    float4 bb1 = *(const float4*)(bias + col0 + tx8 + 4);
#pragma unroll
    for (int i = 0; i < 8; i++) {
        size_t off = (size_t)(row0 + ty8 + i) * DOUT + col0 + tx8;
        float4 v0 = make_float4(acc[i][0] + bb0.x, acc[i][1] + bb0.y,
                                acc[i][2] + bb0.z, acc[i][3] + bb0.w);
        float4 v1 = make_float4(acc[i][4] + bb1.x, acc[i][5] + bb1.y,
                                acc[i][6] + bb1.z, acc[i][7] + bb1.w);
        *(float4*)(out + off)     = v0;
        *(float4*)(out + off + 4) = v1;
    }
}

// ---------------------------------------------------------------------------
extern "C" void kernel_launch(void* const* d_in, const int* in_sizes, int n_in,
                              void* d_out, int out_size) {
    const float* x  = (const float*)d_in[0];   // [4,2048,4096]
    const float* Wb = (const float*)d_in[1];   // [4096,4096]
    const float* bb = (const float*)d_in[2];   // [4096]
    const float* Wr = (const float*)d_in[3];   // [8,4096]
    const float* A  = (const float*)d_in[4];   // [8,16,4096]
    const float* B  = (const float*)d_in[5];   // [8,4096,16]
    float* out = (float*)d_out;                // [4,2048,4096] f32

    router_kernel<<<TT / 8, 256>>>(x, Wr);
    bt_kernel<<<(ERD * DOUT + 255) / 256, 256>>>(B);
    lora_down_kernel<<<TT / 32, 256>>>(x, A);
    dim3 grid(DOUT / 128, TT / 128);
    fused_gemm_kernel<<<grid, 256>>>(x, Wb, bb, out);
}

// round 3
// speedup vs baseline: 3.2813x; 3.2813x over previous
#include <cuda_runtime.h>
#include <cuda_bf16.h>
#include <cstdint>
#include <cstddef>

#define TT   8192
#define DIN  4096
#define DOUT 4096
#define KAUG 4224          // DIN + NE*RNK
#define NE   8
#define RNK  16
#define ERD  128           // NE * RNK
#define SCAL 2.0f

#define NSTAGE 3
#define STAGE  65536       // Ah 16K | Al 16K | Bh 16K | Bl 16K
#define SMEMSZ (1024 + NSTAGE * STAGE)

// ---------------- scratch (__device__ globals; allocation-free rule) --------
__device__ __nv_bfloat16 g_Xh[(size_t)TT * KAUG];   // [x | G] hi
__device__ __nv_bfloat16 g_Xl[(size_t)TT * KAUG];   // [x | G] lo
__device__ __nv_bfloat16 g_Wh[(size_t)DOUT * KAUG]; // [W | Bt] hi
__device__ __nv_bfloat16 g_Wl[(size_t)DOUT * KAUG]; // [W | Bt] lo
__device__ __nv_bfloat16 g_Ah[(size_t)ERD * DIN];   // LoRA A hi
__device__ __nv_bfloat16 g_Al[(size_t)ERD * DIN];   // LoRA A lo
__device__ float g_w[TT * NE];                      // dense router weights

// ---------------- PTX helpers (all plain-sm_103-legal) ----------------------
#define CP_ASYNC16(dst, src) \
    asm volatile("cp.async.cg.shared.global [%0], [%1], 16;" \
                 :: "r"(dst), "l"(src) : "memory")
#define CP_COMMIT() asm volatile("cp.async.commit_group;" ::: "memory")
#define CP_WAIT(n)  asm volatile("cp.async.wait_group %0;" :: "n"(n) : "memory")

__device__ __forceinline__ void ldsm4(uint32_t* r, uint32_t addr) {
    asm volatile("ldmatrix.sync.aligned.m8n8.x4.shared.b16 {%0,%1,%2,%3}, [%4];"
                 : "=r"(r[0]), "=r"(r[1]), "=r"(r[2]), "=r"(r[3]) : "r"(addr));
}

__device__ __forceinline__ void mma_bf16(float* d, const uint32_t* a,
                                         const uint32_t* b) {
    asm volatile(
        "mma.sync.aligned.m16n8k16.row.col.f32.bf16.bf16.f32 "
        "{%0,%1,%2,%3},{%4,%5,%6,%7},{%8,%9},{%0,%1,%2,%3};"
        : "+f"(d[0]), "+f"(d[1]), "+f"(d[2]), "+f"(d[3])
        : "r"(a[0]), "r"(a[1]), "r"(a[2]), "r"(a[3]), "r"(b[0]), "r"(b[1]));
}

// ---------------------------------------------------------------------------
// Router: logits = x @ Wr^T, top-2 softmax -> dense g_w (one warp/token)
// ---------------------------------------------------------------------------
__global__ void router_kernel(const float* __restrict__ x,
                              const float* __restrict__ Wr) {
    int gw   = (blockIdx.x * blockDim.x + threadIdx.x) >> 5;
    int lane = threadIdx.x & 31;
    if (gw >= TT) return;
    const float* xr = x + (size_t)gw * DIN;
    float acc[NE];
#pragma unroll
    for (int e = 0; e < NE; e++) acc[e] = 0.f;
    for (int d = lane * 4; d < DIN; d += 128) {
        float4 xv = *(const float4*)(xr + d);
#pragma unroll
        for (int e = 0; e < NE; e++) {
            float4 wv = *(const float4*)(Wr + e * DIN + d);
            acc[e] += xv.x * wv.x + xv.y * wv.y + xv.z * wv.z + xv.w * wv.w;
        }
    }
#pragma unroll
    for (int e = 0; e < NE; e++) {
#pragma unroll
        for (int off = 16; off > 0; off >>= 1)
            acc[e] += __shfl_xor_sync(0xffffffffu, acc[e], off);
    }
    if (lane == 0) {
        int i0 = 0; float v0 = acc[0];
#pragma unroll
        for (int e = 1; e < NE; e++) if (acc[e] > v0) { v0 = acc[e]; i0 = e; }
        int i1 = -1; float v1 = -3.4e38f;
#pragma unroll
        for (int e = 0; e < NE; e++) if (e != i0 && acc[e] > v1) { v1 = acc[e]; i1 = e; }
        float e1  = expf(v1 - v0);
        float inv = 1.0f / (1.0f + e1);
#pragma unroll
        for (int e = 0; e < NE; e++) g_w[gw * NE + e] = 0.f;
        g_w[gw * NE + i0] = inv;
        g_w[gw * NE + i1] = e1 * inv;
    }
}

// ---------------------------------------------------------------------------
// fp32 -> (bf16 hi, bf16 lo) split; src rows of DIN, dst rows of ld_dst
// ---------------------------------------------------------------------------
__global__ void cvt_split(const float* __restrict__ src,
                          __nv_bfloat16* __restrict__ dh,
                          __nv_bfloat16* __restrict__ dl,
                          int ld_dst) {
    size_t i8 = ((size_t)blockIdx.x * 256 + threadIdx.x) * 8;
    size_t row = i8 / DIN, k = i8 - row * DIN;
    float f[8];
    *(float4*)(f)     = *(const float4*)(src + i8);
    *(float4*)(f + 4) = *(const float4*)(src + i8 + 4);
    alignas(16) __nv_bfloat16 hb[8], lb[8];
#pragma unroll
    for (int i = 0; i < 8; i++) {
        __nv_bfloat16 h = __float2bfloat16_rn(f[i]);
        hb[i] = h;
        lb[i] = __float2bfloat16_rn(f[i] - __bfloat162float(h));
    }
    size_t off = row * (size_t)ld_dst + k;
    *(uint4*)(dh + off) = *(const uint4*)hb;
    *(uint4*)(dl + off) = *(const uint4*)lb;
}

// ---------------------------------------------------------------------------
// Bt into augmented W columns: g_W{h,l}[o*KAUG + 4096 + j] = B[e, o, r]
// ---------------------------------------------------------------------------
__global__ void bt_cvt(const float* __restrict__ B) {
    int idx = blockIdx.x * 256 + threadIdx.x;       // o*128 + j
    if (idx >= DOUT * ERD) return;
    int o = idx >> 7, j = idx & 127;
    int e = j >> 4, r = j & 15;
    float v = B[((size_t)e * DOUT + o) * RNK + r];
    __nv_bfloat16 h = __float2bfloat16_rn(v);
    size_t off = (size_t)o * KAUG + DIN + j;
    g_Wh[off] = h;
    g_Wl[off] = __float2bfloat16_rn(v - __bfloat162float(h));
}

// ---------------------------------------------------------------------------
// mma.sync bf16 GEMM, 3-term split. BM=BN=128, BK=64, 256 thr (8 warps),
// warp tile 32x64 (m16n8k16). cp.async 3-stage pipeline, SW128 smem.
// MODE 0: out = acc + bias (main fused GEMM)
// MODE 1: acc * router_w * SCAL, bf16-split into augmented X cols (LoRA down)
// ---------------------------------------------------------------------------
template<int MODE>
__global__ __launch_bounds__(256)
void gemm_mma(const __nv_bfloat16* __restrict__ Ah,
              const __nv_bfloat16* __restrict__ Al, int lda,
              const __nv_bfloat16* __restrict__ Bh,
              const __nv_bfloat16* __restrict__ Bl, int ldb,
              int nk, const float* __restrict__ bias,
              float* __restrict__ out) {
    extern __shared__ char dsm[];
    uint32_t base = ((uint32_t)__cvta_generic_to_shared(dsm) + 1023u) & ~1023u;
    const int tid  = threadIdx.x;
    const int lane = tid & 31, w = tid >> 5;
    const int wm = w & 3, wn = w >> 2;
    const int row0 = blockIdx.y << 7, col0 = blockIdx.x << 7;

    const __nv_bfloat16* Ahp = Ah + (size_t)row0 * lda;
    const __nv_bfloat16* Alp = Al + (size_t)row0 * lda;
    const __nv_bfloat16* Bhp = Bh + (size_t)col0 * ldb;
    const __nv_bfloat16* Blp = Bl + (size_t)col0 * ldb;

    float acc[2][8][4];
#pragma unroll
    for (int i = 0; i < 2; i++)
#pragma unroll
        for (int j = 0; j < 8; j++)
#pragma unroll
            for (int q = 0; q < 4; q++) acc[i][j][q] = 0.f;

    auto load_stage = [&](int st, int c) {
        uint32_t sb = base + st * STAGE;
        int k0 = c * 64;
#pragma unroll
        for (int i = 0; i < 4; i++) {
            int idx = tid + i * 256;
            int r = idx >> 3, cc = idx & 7;
            uint32_t so = (uint32_t)(r * 128 + ((cc * 16) ^ ((r & 7) * 16)));
            size_t ga = (size_t)r * lda + k0 + cc * 8;
            size_t gb = (size_t)r * ldb + k0 + cc * 8;
            CP_ASYNC16(sb + so,         Ahp + ga);
            CP_ASYNC16(sb + 16384 + so, Alp + ga);
            CP_ASYNC16(sb + 32768 + so, Bhp + gb);
            CP_ASYNC16(sb + 49152 + so, Blp + gb);
        }
    };

    // prologue: stages 0..NSTAGE-2
    load_stage(0, 0); CP_COMMIT();
    load_stage(1, 1); CP_COMMIT();

    const int quad = lane >> 3, lr = lane & 7;
    const int arow0 = wm * 32 + (quad & 1) * 8 + lr;   // + mb*16
    const int akb0  = (quad >> 1) * 8;                 // + ks*16
    const int brow0 = wn * 64 + (quad >> 1) * 8 + lr;  // + nb16*16
    const int bkb0  = (quad & 1) * 8;

    for (int c = 0; c < nk; c++) {
        CP_WAIT(1);
        __syncthreads();
        int cn = c + NSTAGE - 1;
        if (cn < nk) load_stage(cn % NSTAGE, cn);
        CP_COMMIT();

        uint32_t sb = base + (c % NSTAGE) * STAGE;
#pragma unroll
        for (int ks = 0; ks < 4; ks++) {
            uint32_t ah[2][4], al[2][4], bfr[8][2];
            // A offsets for this k-step
            uint32_t aoff[2];
#pragma unroll
            for (int mb = 0; mb < 2; mb++) {
                int row = arow0 + mb * 16;
                aoff[mb] = (uint32_t)(row * 128 +
                           (((akb0 + ks * 16) * 2) ^ ((row & 7) * 16)));
            }
            // B-hi fragments (4 x4 = 8 n8-fragments)
#pragma unroll
            for (int nb = 0; nb < 4; nb++) {
                int row = brow0 + nb * 16;
                uint32_t off = (uint32_t)(row * 128 +
                               (((bkb0 + ks * 16) * 2) ^ ((row & 7) * 16)));
                uint32_t t4[4];
                ldsm4(t4, sb + 32768 + off);
                bfr[2 * nb][0] = t4[0]; bfr[2 * nb][1] = t4[1];
                bfr[2 * nb + 1][0] = t4[2]; bfr[2 * nb + 1][1] = t4[3];
            }
            // A-hi, A-lo
#pragma unroll
            for (int mb = 0; mb < 2; mb++) {
                ldsm4(ah[mb], sb + aoff[mb]);
                ldsm4(al[mb], sb + 16384 + aoff[mb]);
            }
            // pass 1: Ah x Bh ; pass 2: Al x Bh
#pragma unroll
            for (int mb = 0; mb < 2; mb++)
#pragma unroll
                for (int nb = 0; nb < 8; nb++)
                    mma_bf16(acc[mb][nb], ah[mb], bfr[nb]);
#pragma unroll
            for (int mb = 0; mb < 2; mb++)
#pragma unroll
                for (int nb = 0; nb < 8; nb++)
                    mma_bf16(acc[mb][nb], al[mb], bfr[nb]);
            // B-lo fragments, pass 3: Ah x Bl
#pragma unroll
            for (int nb = 0; nb < 4; nb++) {
                int row = brow0 + nb * 16;
                uint32_t off = (uint32_t)(row * 128 +
                               (((bkb0 + ks * 16) * 2) ^ ((row & 7) * 16)));
                uint32_t t4[4];
                ldsm4(t4, sb + 49152 + off);
                bfr[2 * nb][0] = t4[0]; bfr[2 * nb][1] = t4[1];
                bfr[2 * nb + 1][0] = t4[2]; bfr[2 * nb + 1][1] = t4[3];
            }
#pragma unroll
            for (int mb = 0; mb < 2; mb++)
#pragma unroll
                for (int nb = 0; nb < 8; nb++)
                    mma_bf16(acc[mb][nb], ah[mb], bfr[nb]);
        }
    }

    // ---------------- epilogue ----------------
    const int g = lane >> 2, t4i = lane & 3;
#pragma unroll
    for (int mb = 0; mb < 2; mb++) {
        int grow = row0 + wm * 32 + mb * 16 + g;
#pragma unroll
        for (int half = 0; half < 2; half++) {
            int r = grow + half * 8;
            if (MODE == 0) {
#pragma unroll
                for (int nb = 0; nb < 8; nb++) {
                    int gcol = col0 + wn * 64 + nb * 8 + t4i * 2;
                    float2 bb = *(const float2*)(bias + gcol);
                    float2 v;
                    v.x = acc[mb][nb][half * 2 + 0] + bb.x;
                    v.y = acc[mb][nb][half * 2 + 1] + bb.y;
                    *(float2*)(out + (size_t)r * DOUT + gcol) = v;
                }
            } else {
#pragma unroll
                for (int nb = 0; nb < 8; nb++) {
                    int cfull = wn * 64 + nb * 8 + t4i * 2;   // 0..127
                    float ww = g_w[r * NE + (cfull >> 4)] * SCAL;
                    float a = acc[mb][nb][half * 2 + 0] * ww;
                    float b = acc[mb][nb][half * 2 + 1] * ww;
                    __nv_bfloat16 ha = __float2bfloat16_rn(a);
                    __nv_bfloat16 hb = __float2bfloat16_rn(b);
                    __nv_bfloat162 hh, ll;
                    hh.x = ha; hh.y = hb;
                    ll.x = __float2bfloat16_rn(a - __bfloat162float(ha));
                    ll.y = __float2bfloat16_rn(b - __bfloat162float(hb));
                    size_t off = (size_t)r * KAUG + DIN + cfull;
                    *(__nv_bfloat162*)(g_Xh + off) = hh;
                    *(__nv_bfloat162*)(g_Xl + off) = ll;
                }
            }
        }
    }
}

// ---------------------------------------------------------------------------
extern "C" void kernel_launch(void* const* d_in, const int* in_sizes, int n_in,
                              void* d_out, int out_size) {
    const float* x  = (const float*)d_in[0];   // [4,2048,4096]
    const float* Wb = (const float*)d_in[1];   // [4096,4096]
    const float* bb = (const float*)d_in[2];   // [4096]
    const float* Wr = (const float*)d_in[3];   // [8,4096]
    const float* A  = (const float*)d_in[4];   // [8,16,4096] == [ERD, DIN]
    const float* B  = (const float*)d_in[5];   // [8,4096,16]
    float* out = (float*)d_out;

    void *pXh, *pXl, *pWh, *pWl, *pAh, *pAl;
    cudaGetSymbolAddress(&pXh, g_Xh);
    cudaGetSymbolAddress(&pXl, g_Xl);
    cudaGetSymbolAddress(&pWh, g_Wh);
    cudaGetSymbolAddress(&pWl, g_Wl);
    cudaGetSymbolAddress(&pAh, g_Ah);
    cudaGetSymbolAddress(&pAl, g_Al);

    cudaFuncSetAttribute(gemm_mma<0>,
        cudaFuncAttributeMaxDynamicSharedMemorySize, SMEMSZ);
    cudaFuncSetAttribute(gemm_mma<1>,
        cudaFuncAttributeMaxDynamicSharedMemorySize, SMEMSZ);

    router_kernel<<<TT / 8, 256>>>(x, Wr);
    cvt_split<<<TT * DIN / 8 / 256, 256>>>(x, (__nv_bfloat16*)pXh,
                                           (__nv_bfloat16*)pXl, KAUG);
    cvt_split<<<ERD * DIN / 8 / 256, 256>>>(A, (__nv_bfloat16*)pAh,
                                            (__nv_bfloat16*)pAl, DIN);
    cvt_split<<<DOUT * DIN / 8 / 256, 256>>>(Wb, (__nv_bfloat16*)pWh,
                                             (__nv_bfloat16*)pWl, KAUG);
    bt_cvt<<<DOUT * ERD / 256, 256>>>(B);

    // LoRA down-projection: G = softmax-weighted (x @ A^T), split into
    // augmented X columns [4096..4224)
    gemm_mma<1><<<dim3(1, TT / 128), 256, SMEMSZ>>>(
        (const __nv_bfloat16*)pXh, (const __nv_bfloat16*)pXl, KAUG,
        (const __nv_bfloat16*)pAh, (const __nv_bfloat16*)pAl, DIN,
        DIN / 64, nullptr, nullptr);

    // Main fused GEMM: out = [x|G] @ [W|Bt]^T + bias
    gemm_mma<0><<<dim3(DOUT / 128, TT / 128), 256, SMEMSZ>>>(
        (const __nv_bfloat16*)pXh, (const __nv_bfloat16*)pXl, KAUG,
        (const __nv_bfloat16*)pWh, (const __nv_bfloat16*)pWl, KAUG,
        KAUG / 64, bb, out);
}

// round 4
// speedup vs baseline: 3.4893x; 1.0634x over previous
#include <cuda_runtime.h>
#include <cuda_bf16.h>
#include <cstdint>
#include <cstddef>

#define TT   8192
#define DIN  4096
#define DOUT 4096
#define KAUG 4224          // DIN + NE*RNK
#define NE   8
#define RNK  16
#define ERD  128           // NE * RNK
#define SCAL 2.0f

// ---------------- scratch (__device__ globals; allocation-free rule) --------
__device__ __nv_bfloat16 g_Xh[(size_t)TT * KAUG];   // [x | G] hi
__device__ __nv_bfloat16 g_Xl[(size_t)TT * KAUG];   // [x | G] lo
__device__ __nv_bfloat16 g_Wh[(size_t)DOUT * KAUG]; // [W | Bt] hi
__device__ __nv_bfloat16 g_Wl[(size_t)DOUT * KAUG]; // [W | Bt] lo
__device__ __nv_bfloat16 g_Ah[(size_t)ERD * DIN];   // LoRA A hi
__device__ __nv_bfloat16 g_Al[(size_t)ERD * DIN];   // LoRA A lo
__device__ float g_w[TT * NE];                      // dense router weights

// ---------------- PTX helpers (plain-sm_103-legal) --------------------------
#define CP_ASYNC16(dst, src) \
    asm volatile("cp.async.cg.shared.global [%0], [%1], 16;" \
                 :: "r"(dst), "l"(src) : "memory")
#define CP_COMMIT() asm volatile("cp.async.commit_group;" ::: "memory")
#define CP_WAIT0()  asm volatile("cp.async.wait_group 0;" ::: "memory")

__device__ __forceinline__ void ldsm4(uint32_t* r, uint32_t addr) {
    asm volatile("ldmatrix.sync.aligned.m8n8.x4.shared.b16 {%0,%1,%2,%3}, [%4];"
                 : "=r"(r[0]), "=r"(r[1]), "=r"(r[2]), "=r"(r[3]) : "r"(addr));
}

__device__ __forceinline__ void mma_bf16(float* d, const uint32_t* a,
                                         const uint32_t* b) {
    asm volatile(
        "mma.sync.aligned.m16n8k16.row.col.f32.bf16.bf16.f32 "
        "{%0,%1,%2,%3},{%4,%5,%6,%7},{%8,%9},{%0,%1,%2,%3};"
        : "+f"(d[0]), "+f"(d[1]), "+f"(d[2]), "+f"(d[3])
        : "r"(a[0]), "r"(a[1]), "r"(a[2]), "r"(a[3]), "r"(b[0]), "r"(b[1]));
}

// ---------------------------------------------------------------------------
// Router: logits = x @ Wr^T, top-2 softmax -> dense g_w (one warp/token)
// ---------------------------------------------------------------------------
__global__ void router_kernel(const float* __restrict__ x,
                              const float* __restrict__ Wr) {
    int gw   = (blockIdx.x * blockDim.x + threadIdx.x) >> 5;
    int lane = threadIdx.x & 31;
    if (gw >= TT) return;
    const float* xr = x + (size_t)gw * DIN;
    float acc[NE];
#pragma unroll
    for (int e = 0; e < NE; e++) acc[e] = 0.f;
    for (int d = lane * 4; d < DIN; d += 128) {
        float4 xv = *(const float4*)(xr + d);
#pragma unroll
        for (int e = 0; e < NE; e++) {
            float4 wv = *(const float4*)(Wr + e * DIN + d);
            acc[e] += xv.x * wv.x + xv.y * wv.y + xv.z * wv.z + xv.w * wv.w;
        }
    }
#pragma unroll
    for (int e = 0; e < NE; e++) {
#pragma unroll
        for (int off = 16; off > 0; off >>= 1)
            acc[e] += __shfl_xor_sync(0xffffffffu, acc[e], off);
    }
    if (lane == 0) {
        int i0 = 0; float v0 = acc[0];
#pragma unroll
        for (int e = 1; e < NE; e++) if (acc[e] > v0) { v0 = acc[e]; i0 = e; }
        int i1 = -1; float v1 = -3.4e38f;
#pragma unroll
        for (int e = 0; e < NE; e++) if (e != i0 && acc[e] > v1) { v1 = acc[e]; i1 = e; }
        float e1  = expf(v1 - v0);
        float inv = 1.0f / (1.0f + e1);
#pragma unroll
        for (int e = 0; e < NE; e++) g_w[gw * NE + e] = 0.f;
        g_w[gw * NE + i0] = inv;
        g_w[gw * NE + i1] = e1 * inv;
    }
}

// ---------------------------------------------------------------------------
// fp32 -> (bf16 hi, bf16 lo) split; src rows of DIN, dst rows of ld_dst
// ---------------------------------------------------------------------------
__global__ void cvt_split(const float* __restrict__ src,
                          __nv_bfloat16* __restrict__ dh,
                          __nv_bfloat16* __restrict__ dl,
                          int ld_dst) {
    size_t i8 = ((size_t)blockIdx.x * 256 + threadIdx.x) * 8;
    size_t row = i8 / DIN, k = i8 - row * DIN;
    float f[8];
    *(float4*)(f)     = *(const float4*)(src + i8);
    *(float4*)(f + 4) = *(const float4*)(src + i8 + 4);
    alignas(16) __nv_bfloat16 hb[8], lb[8];
#pragma unroll
    for (int i = 0; i < 8; i++) {
        __nv_bfloat16 h = __float2bfloat16_rn(f[i]);
        hb[i] = h;
        lb[i] = __float2bfloat16_rn(f[i] - __bfloat162float(h));
    }
    size_t off = row * (size_t)ld_dst + k;
    *(uint4*)(dh + off) = *(const uint4*)hb;
    *(uint4*)(dl + off) = *(const uint4*)lb;
}

// ---------------------------------------------------------------------------
// Bt into augmented W columns: g_W{h,l}[o*KAUG + 4096 + j] = B[e, o, r]
// ---------------------------------------------------------------------------
__global__ void bt_cvt(const float* __restrict__ B) {
    int idx = blockIdx.x * 256 + threadIdx.x;       // o*128 + j
    if (idx >= DOUT * ERD) return;
    int o = idx >> 7, j = idx & 127;
    int e = j >> 4, r = j & 15;
    float v = B[((size_t)e * DOUT + o) * RNK + r];
    __nv_bfloat16 h = __float2bfloat16_rn(v);
    size_t off = (size_t)o * KAUG + DIN + j;
    g_Wh[off] = h;
    g_Wl[off] = __float2bfloat16_rn(v - __bfloat162float(h));
}

// ---------------------------------------------------------------------------
// mma.sync bf16 GEMM, 3-term split. BM = 32*BMQ, BN = 128, BK = 64,
// 64*BMQ threads, warp tile 32x64. 2-stage cp.async pipeline, SW128 smem.
// MODE 0: out = acc + bias (main fused GEMM)
// MODE 1: acc * router_w * SCAL, bf16-split into augmented X cols (LoRA down)
// ---------------------------------------------------------------------------
template<int BMQ, int MODE>
__global__ __launch_bounds__(64 * BMQ, 1)
void gemm_mma(const __nv_bfloat16* __restrict__ Ah,
              const __nv_bfloat16* __restrict__ Al, int lda,
              const __nv_bfloat16* __restrict__ Bh,
              const __nv_bfloat16* __restrict__ Bl, int ldb,
              int nk, const float* __restrict__ bias,
              float* __restrict__ out) {
    constexpr int THREADS = 64 * BMQ;
    constexpr int BM      = 32 * BMQ;
    constexpr int OFF_AL  = BM * 128;        // bytes per A tile (BM x 64 bf16)
    constexpr int OFF_BH  = 2 * BM * 128;
    constexpr int OFF_BL  = OFF_BH + 16384;
    constexpr int STAGE   = OFF_BH + 32768;
    constexpr int NBI     = 1024 / THREADS;  // B-tile 16B chunks per thread

    extern __shared__ char dsm[];
    uint32_t base = ((uint32_t)__cvta_generic_to_shared(dsm) + 1023u) & ~1023u;
    const int tid  = threadIdx.x;
    const int lane = tid & 31, w = tid >> 5;
    const int wm = w % BMQ, wn = w / BMQ;
    const int row0 = blockIdx.y * BM, col0 = blockIdx.x << 7;

    const __nv_bfloat16* Ahp = Ah + (size_t)row0 * lda;
    const __nv_bfloat16* Alp = Al + (size_t)row0 * lda;
    const __nv_bfloat16* Bhp = Bh + (size_t)col0 * ldb;
    const __nv_bfloat16* Blp = Bl + (size_t)col0 * ldb;

    float acc[2][8][4];
#pragma unroll
    for (int i = 0; i < 2; i++)
#pragma unroll
        for (int j = 0; j < 8; j++)
#pragma unroll
            for (int q = 0; q < 4; q++) acc[i][j][q] = 0.f;

    auto load_stage = [&](int st, int c) {
        uint32_t sb = base + st * STAGE;
        int k0 = c * 64;
#pragma unroll
        for (int i = 0; i < 4; i++) {               // A: BM*8 chunks
            int idx = tid + i * THREADS;
            int r = idx >> 3, cc = idx & 7;
            uint32_t so = (uint32_t)(r * 128 + ((cc * 16) ^ ((r & 7) * 16)));
            size_t ga = (size_t)r * lda + k0 + cc * 8;
            CP_ASYNC16(sb + so,          Ahp + ga);
            CP_ASYNC16(sb + OFF_AL + so, Alp + ga);
        }
#pragma unroll
        for (int i = 0; i < NBI; i++) {             // B: 1024 chunks
            int idx = tid + i * THREADS;
            int r = idx >> 3, cc = idx & 7;
            uint32_t so = (uint32_t)(r * 128 + ((cc * 16) ^ ((r & 7) * 16)));
            size_t gb = (size_t)r * ldb + k0 + cc * 8;
            CP_ASYNC16(sb + OFF_BH + so, Bhp + gb);
            CP_ASYNC16(sb + OFF_BL + so, Blp + gb);
        }
    };

    load_stage(0, 0); CP_COMMIT();

    const int quad = lane >> 3, lr = lane & 7;
    const int arow0 = wm * 32 + (quad & 1) * 8 + lr;   // + mb*16
    const int akb0  = (quad >> 1) * 8;                 // + ks*16
    const int brow0 = wn * 64 + (quad >> 1) * 8 + lr;  // + nb16*16
    const int bkb0  = (quad & 1) * 8;

    for (int c = 0; c < nk; c++) {
        CP_WAIT0();
        __syncthreads();
        if (c + 1 < nk) { load_stage((c + 1) & 1, c + 1); CP_COMMIT(); }

        uint32_t sb = base + (c & 1) * STAGE;
#pragma unroll
        for (int ks = 0; ks < 4; ks++) {
            uint32_t ah[2][4], al[2][4], bfr[8][2];
            uint32_t aoff[2];
#pragma unroll
            for (int mb = 0; mb < 2; mb++) {
                int row = arow0 + mb * 16;
                aoff[mb] = (uint32_t)(row * 128 +
                           (((akb0 + ks * 16) * 2) ^ ((row & 7) * 16)));
            }
#pragma unroll
            for (int nb = 0; nb < 4; nb++) {
                int row = brow0 + nb * 16;
                uint32_t off = (uint32_t)(row * 128 +
                               (((bkb0 + ks * 16) * 2) ^ ((row & 7) * 16)));
                uint32_t t4[4];
                ldsm4(t4, sb + OFF_BH + off);
                bfr[2 * nb][0] = t4[0]; bfr[2 * nb][1] = t4[1];
                bfr[2 * nb + 1][0] = t4[2]; bfr[2 * nb + 1][1] = t4[3];
            }
#pragma unroll
            for (int mb = 0; mb < 2; mb++) {
                ldsm4(ah[mb], sb + aoff[mb]);
                ldsm4(al[mb], sb + OFF_AL + aoff[mb]);
            }
#pragma unroll
            for (int mb = 0; mb < 2; mb++)
#pragma unroll
                for (int nb = 0; nb < 8; nb++)
                    mma_bf16(acc[mb][nb], ah[mb], bfr[nb]);
#pragma unroll
            for (int mb = 0; mb < 2; mb++)
#pragma unroll
                for (int nb = 0; nb < 8; nb++)
                    mma_bf16(acc[mb][nb], al[mb], bfr[nb]);
#pragma unroll
            for (int nb = 0; nb < 4; nb++) {
                int row = brow0 + nb * 16;
                uint32_t off = (uint32_t)(row * 128 +
                               (((bkb0 + ks * 16) * 2) ^ ((row & 7) * 16)));
                uint32_t t4[4];
                ldsm4(t4, sb + OFF_BL + off);
                bfr[2 * nb][0] = t4[0]; bfr[2 * nb][1] = t4[1];
                bfr[2 * nb + 1][0] = t4[2]; bfr[2 * nb + 1][1] = t4[3];
            }
#pragma unroll
            for (int mb = 0; mb < 2; mb++)
#pragma unroll
                for (int nb = 0; nb < 8; nb++)
                    mma_bf16(acc[mb][nb], ah[mb], bfr[nb]);
        }
    }

    // ---------------- epilogue ----------------
    const int g = lane >> 2, t4i = lane & 3;
#pragma unroll
    for (int mb = 0; mb < 2; mb++) {
        int grow = row0 + wm * 32 + mb * 16 + g;
#pragma unroll
        for (int half = 0; half < 2; half++) {
            int r = grow + half * 8;
            if (MODE == 0) {
#pragma unroll
                for (int nb = 0; nb < 8; nb++) {
                    int gcol = col0 + wn * 64 + nb * 8 + t4i * 2;
                    float2 bb = *(const float2*)(bias + gcol);
                    float2 v;
                    v.x = acc[mb][nb][half * 2 + 0] + bb.x;
                    v.y = acc[mb][nb][half * 2 + 1] + bb.y;
                    *(float2*)(out + (size_t)r * DOUT + gcol) = v;
                }
            } else {
#pragma unroll
                for (int nb = 0; nb < 8; nb++) {
                    int cfull = wn * 64 + nb * 8 + t4i * 2;   // 0..127
                    float ww = g_w[r * NE + (cfull >> 4)] * SCAL;
                    float a = acc[mb][nb][half * 2 + 0] * ww;
                    float b = acc[mb][nb][half * 2 + 1] * ww;
                    __nv_bfloat16 ha = __float2bfloat16_rn(a);
                    __nv_bfloat16 hb = __float2bfloat16_rn(b);
                    __nv_bfloat162 hh, ll;
                    hh.x = ha; hh.y = hb;
                    ll.x = __float2bfloat16_rn(a - __bfloat162float(ha));
                    ll.y = __float2bfloat16_rn(b - __bfloat162float(hb));
                    size_t off = (size_t)r * KAUG + DIN + cfull;
                    *(__nv_bfloat162*)(g_Xh + off) = hh;
                    *(__nv_bfloat162*)(g_Xl + off) = ll;
                }
            }
        }
    }
}

// ---------------------------------------------------------------------------
extern "C" void kernel_launch(void* const* d_in, const int* in_sizes, int n_in,
                              void* d_out, int out_size) {
    const float* x  = (const float*)d_in[0];   // [4,2048,4096]
    const float* Wb = (const float*)d_in[1];   // [4096,4096]
    const float* bb = (const float*)d_in[2];   // [4096]
    const float* Wr = (const float*)d_in[3];   // [8,4096]
    const float* A  = (const float*)d_in[4];   // [8,16,4096] == [ERD, DIN]
    const float* B  = (const float*)d_in[5];   // [8,4096,16]
    float* out = (float*)d_out;

    void *pXh, *pXl, *pWh, *pWl, *pAh, *pAl;
    cudaGetSymbolAddress(&pXh, g_Xh);
    cudaGetSymbolAddress(&pXl, g_Xl);
    cudaGetSymbolAddress(&pWh, g_Wh);
    cudaGetSymbolAddress(&pWl, g_Wl);
    cudaGetSymbolAddress(&pAh, g_Ah);
    cudaGetSymbolAddress(&pAl, g_Al);

    // smem: 1024 pad + 2 stages
    const int smem_main = 1024 + 2 * (2 * 256 * 128 + 32768);   // 197632
    const int smem_lora = 1024 + 2 * (2 * 128 * 128 + 32768);   // 132096
    cudaFuncSetAttribute(gemm_mma<8, 0>,
        cudaFuncAttributeMaxDynamicSharedMemorySize, smem_main);
    cudaFuncSetAttribute(gemm_mma<4, 1>,
        cudaFuncAttributeMaxDynamicSharedMemorySize, smem_lora);

    router_kernel<<<TT / 8, 256>>>(x, Wr);
    cvt_split<<<TT * DIN / 8 / 256, 256>>>(x, (__nv_bfloat16*)pXh,
                                           (__nv_bfloat16*)pXl, KAUG);
    cvt_split<<<ERD * DIN / 8 / 256, 256>>>(A, (__nv_bfloat16*)pAh,
                                            (__nv_bfloat16*)pAl, DIN);
    cvt_split<<<DOUT * DIN / 8 / 256, 256>>>(Wb, (__nv_bfloat16*)pWh,
                                             (__nv_bfloat16*)pWl, KAUG);
    bt_cvt<<<DOUT * ERD / 256, 256>>>(B);

    // LoRA down-projection: G = softmax-weighted (x @ A^T), split into
    // augmented X columns [4096..4224)
    gemm_mma<4, 1><<<dim3(1, TT / 128), 256, smem_lora>>>(
        (const __nv_bfloat16*)pXh, (const __nv_bfloat16*)pXl, KAUG,
        (const __nv_bfloat16*)pAh, (const __nv_bfloat16*)pAl, DIN,
        DIN / 64, nullptr, nullptr);

    // Main fused GEMM: out = [x|G] @ [W|Bt]^T + bias
    gemm_mma<8, 0><<<dim3(DOUT / 128, TT / 256), 512, smem_main>>>(
        (const __nv_bfloat16*)pXh, (const __nv_bfloat16*)pXl, KAUG,
        (const __nv_bfloat16*)pWh, (const __nv_bfloat16*)pWl, KAUG,
        KAUG / 64, bb, out);
}

// round 5
// speedup vs baseline: 7.7639x; 2.2251x over previous
#include <cuda_runtime.h>
#include <cuda_fp16.h>
#include <cstdint>
#include <cstddef>

#define TT   8192
#define DIN  4096
#define DOUT 4096
#define KAUG 4224          // DIN + NE*RNK
#define NE   8
#define RNK  16
#define ERD  128           // NE * RNK
#define SCAL 2.0f

// ---------------- scratch (__device__ globals; allocation-free rule) --------
__device__ __half g_X[(size_t)TT * KAUG];    // [x | G] fp16
__device__ __half g_W[(size_t)DOUT * KAUG];  // [W | Bt] fp16
__device__ __half g_A[(size_t)ERD * DIN];    // LoRA A fp16
__device__ float  g_w[TT * NE];              // dense router weights

// ---------------- PTX helpers (plain-sm_103-legal) --------------------------
#define CP_ASYNC16(dst, src) \
    asm volatile("cp.async.cg.shared.global [%0], [%1], 16;" \
                 :: "r"(dst), "l"(src) : "memory")
#define CP_COMMIT() asm volatile("cp.async.commit_group;" ::: "memory")
#define CP_WAIT1()  asm volatile("cp.async.wait_group 1;" ::: "memory")

__device__ __forceinline__ void ldsm4(uint32_t* r, uint32_t addr) {
    asm volatile("ldmatrix.sync.aligned.m8n8.x4.shared.b16 {%0,%1,%2,%3}, [%4];"
                 : "=r"(r[0]), "=r"(r[1]), "=r"(r[2]), "=r"(r[3]) : "r"(addr));
}

__device__ __forceinline__ void mma_f16(float* d, const uint32_t* a,
                                        const uint32_t* b) {
    asm volatile(
        "mma.sync.aligned.m16n8k16.row.col.f32.f16.f16.f32 "
        "{%0,%1,%2,%3},{%4,%5,%6,%7},{%8,%9},{%0,%1,%2,%3};"
        : "+f"(d[0]), "+f"(d[1]), "+f"(d[2]), "+f"(d[3])
        : "r"(a[0]), "r"(a[1]), "r"(a[2]), "r"(a[3]), "r"(b[0]), "r"(b[1]));
}

// ---------------------------------------------------------------------------
// Router: logits = x @ Wr^T, top-2 softmax -> dense g_w (one warp/token)
// ---------------------------------------------------------------------------
__global__ void router_kernel(const float* __restrict__ x,
                              const float* __restrict__ Wr) {
    int gw   = (blockIdx.x * blockDim.x + threadIdx.x) >> 5;
    int lane = threadIdx.x & 31;
    if (gw >= TT) return;
    const float* xr = x + (size_t)gw * DIN;
    float acc[NE];
#pragma unroll
    for (int e = 0; e < NE; e++) acc[e] = 0.f;
    for (int d = lane * 4; d < DIN; d += 128) {
        float4 xv = *(const float4*)(xr + d);
#pragma unroll
        for (int e = 0; e < NE; e++) {
            float4 wv = *(const float4*)(Wr + e * DIN + d);
            acc[e] += xv.x * wv.x + xv.y * wv.y + xv.z * wv.z + xv.w * wv.w;
        }
    }
#pragma unroll
    for (int e = 0; e < NE; e++) {
#pragma unroll
        for (int off = 16; off > 0; off >>= 1)
            acc[e] += __shfl_xor_sync(0xffffffffu, acc[e], off);
    }
    if (lane == 0) {
        int i0 = 0; float v0 = acc[0];
#pragma unroll
        for (int e = 1; e < NE; e++) if (acc[e] > v0) { v0 = acc[e]; i0 = e; }
        int i1 = -1; float v1 = -3.4e38f;
#pragma unroll
        for (int e = 0; e < NE; e++) if (e != i0 && acc[e] > v1) { v1 = acc[e]; i1 = e; }
        float e1  = expf(v1 - v0);
        float inv = 1.0f / (1.0f + e1);
#pragma unroll
        for (int e = 0; e < NE; e++) g_w[gw * NE + e] = 0.f;
        g_w[gw * NE + i0] = inv;
        g_w[gw * NE + i1] = e1 * inv;
    }
}

// ---------------------------------------------------------------------------
// fp32 -> fp16 convert; src rows of DIN, dst rows of ld_dst
// ---------------------------------------------------------------------------
__global__ void cvt_h(const float* __restrict__ src,
                      __half* __restrict__ dst, int ld_dst) {
    size_t i8 = ((size_t)blockIdx.x * 256 + threadIdx.x) * 8;
    size_t row = i8 / DIN, k = i8 - row * DIN;
    float f[8];
    *(float4*)(f)     = *(const float4*)(src + i8);
    *(float4*)(f + 4) = *(const float4*)(src + i8 + 4);
    alignas(16) __half h[8];
#pragma unroll
    for (int i = 0; i < 8; i++) h[i] = __float2half_rn(f[i]);
    *(uint4*)(dst + row * (size_t)ld_dst + k) = *(const uint4*)h;
}

// ---------------------------------------------------------------------------
// Bt into augmented W columns: g_W[o*KAUG + 4096 + j] = B[e, o, r]
// ---------------------------------------------------------------------------
__global__ void bt_cvt(const float* __restrict__ B) {
    int idx = blockIdx.x * 256 + threadIdx.x;       // o*128 + j
    if (idx >= DOUT * ERD) return;
    int o = idx >> 7, j = idx & 127;
    int e = j >> 4, r = j & 15;
    float v = B[((size_t)e * DOUT + o) * RNK + r];
    g_W[(size_t)o * KAUG + DIN + j] = __float2half_rn(v);
}

// ---------------------------------------------------------------------------
// mma.sync fp16 GEMM (single pass). BM = 32*BMQ, BN = 128, BK = 64,
// 64*BMQ threads, warp tile 32x64. 3-stage cp.async pipeline, SW128 smem.
// MODE 0: out = acc + bias (main fused GEMM)
// MODE 1: acc * router_w * SCAL -> fp16 into augmented X cols (LoRA down)
// ---------------------------------------------------------------------------
template<int BMQ, int MODE>
__global__ __launch_bounds__(64 * BMQ, 1)
void gemm_mma(const __half* __restrict__ Ag, int lda,
              const __half* __restrict__ Bg, int ldb,
              int nk, const float* __restrict__ bias,
              float* __restrict__ out) {
    constexpr int THREADS = 64 * BMQ;
    constexpr int BM      = 32 * BMQ;
    constexpr int OFF_B   = BM * 128;        // A tile bytes (BM x 64 fp16)
    constexpr int STAGE   = OFF_B + 16384;   // + B tile (128 x 64 fp16)
    constexpr int NBI     = 1024 / THREADS;  // B-tile 16B chunks per thread

    extern __shared__ char dsm[];
    uint32_t base = ((uint32_t)__cvta_generic_to_shared(dsm) + 1023u) & ~1023u;
    const int tid  = threadIdx.x;
    const int lane = tid & 31, w = tid >> 5;
    const int wm = w % BMQ, wn = w / BMQ;
    const int row0 = blockIdx.y * BM, col0 = blockIdx.x << 7;

    const __half* Ap = Ag + (size_t)row0 * lda;
    const __half* Bp = Bg + (size_t)col0 * ldb;

    float acc[2][8][4];
#pragma unroll
    for (int i = 0; i < 2; i++)
#pragma unroll
        for (int j = 0; j < 8; j++)
#pragma unroll
            for (int q = 0; q < 4; q++) acc[i][j][q] = 0.f;

    auto load_stage = [&](int st, int c) {
        uint32_t sb = base + st * STAGE;
        int k0 = c * 64;
#pragma unroll
        for (int i = 0; i < 4; i++) {               // A: BM*8 chunks
            int idx = tid + i * THREADS;
            int r = idx >> 3, cc = idx & 7;
            uint32_t so = (uint32_t)(r * 128 + ((cc * 16) ^ ((r & 7) * 16)));
            CP_ASYNC16(sb + so, Ap + (size_t)r * lda + k0 + cc * 8);
        }
#pragma unroll
        for (int i = 0; i < NBI; i++) {             // B: 1024 chunks
            int idx = tid + i * THREADS;
            int r = idx >> 3, cc = idx & 7;
            uint32_t so = (uint32_t)(r * 128 + ((cc * 16) ^ ((r & 7) * 16)));
            CP_ASYNC16(sb + OFF_B + so, Bp + (size_t)r * ldb + k0 + cc * 8);
        }
    };

    load_stage(0, 0); CP_COMMIT();
    load_stage(1, 1); CP_COMMIT();

    const int quad = lane >> 3, lr = lane & 7;
    const int arow0 = wm * 32 + (quad & 1) * 8 + lr;   // + mb*16
    const int akb0  = (quad >> 1) * 8;                 // + ks*16
    const int brow0 = wn * 64 + (quad >> 1) * 8 + lr;  // + nb16*16
    const int bkb0  = (quad & 1) * 8;

    for (int c = 0; c < nk; c++) {
        CP_WAIT1();
        __syncthreads();
        if (c + 2 < nk) { load_stage((c + 2) % 3, c + 2); }
        CP_COMMIT();

        uint32_t sb = base + (c % 3) * STAGE;
#pragma unroll
        for (int ks = 0; ks < 4; ks++) {
            uint32_t ah[2][4], bfr[8][2];
#pragma unroll
            for (int nb = 0; nb < 4; nb++) {
                int row = brow0 + nb * 16;
                uint32_t off = (uint32_t)(row * 128 +
                               (((bkb0 + ks * 16) * 2) ^ ((row & 7) * 16)));
                uint32_t t4[4];
                ldsm4(t4, sb + OFF_B + off);
                bfr[2 * nb][0] = t4[0]; bfr[2 * nb][1] = t4[1];
                bfr[2 * nb + 1][0] = t4[2]; bfr[2 * nb + 1][1] = t4[3];
            }
#pragma unroll
            for (int mb = 0; mb < 2; mb++) {
                int row = arow0 + mb * 16;
                uint32_t off = (uint32_t)(row * 128 +
                               (((akb0 + ks * 16) * 2) ^ ((row & 7) * 16)));
                ldsm4(ah[mb], sb + off);
            }
#pragma unroll
            for (int mb = 0; mb < 2; mb++)
#pragma unroll
                for (int nb = 0; nb < 8; nb++)
                    mma_f16(acc[mb][nb], ah[mb], bfr[nb]);
        }
        __syncthreads();
    }

    // ---------------- epilogue ----------------
    const int g = lane >> 2, t4i = lane & 3;
#pragma unroll
    for (int mb = 0; mb < 2; mb++) {
        int grow = row0 + wm * 32 + mb * 16 + g;
#pragma unroll
        for (int half = 0; half < 2; half++) {
            int r = grow + half * 8;
            if (MODE == 0) {
#pragma unroll
                for (int nb = 0; nb < 8; nb++) {
                    int gcol = col0 + wn * 64 + nb * 8 + t4i * 2;
                    float2 bb = *(const float2*)(bias + gcol);
                    float2 v;
                    v.x = acc[mb][nb][half * 2 + 0] + bb.x;
                    v.y = acc[mb][nb][half * 2 + 1] + bb.y;
                    *(float2*)(out + (size_t)r * DOUT + gcol) = v;
                }
            } else {
#pragma unroll
                for (int nb = 0; nb < 8; nb++) {
                    int cfull = wn * 64 + nb * 8 + t4i * 2;   // 0..127
                    float ww = g_w[r * NE + (cfull >> 4)] * SCAL;
                    __half2 hv = __floats2half2_rn(
                        acc[mb][nb][half * 2 + 0] * ww,
                        acc[mb][nb][half * 2 + 1] * ww);
                    *(__half2*)(g_X + (size_t)r * KAUG + DIN + cfull) = hv;
                }
            }
        }
    }
}

// ---------------------------------------------------------------------------
extern "C" void kernel_launch(void* const* d_in, const int* in_sizes, int n_in,
                              void* d_out, int out_size) {
    const float* x  = (const float*)d_in[0];   // [4,2048,4096]
    const float* Wb = (const float*)d_in[1];   // [4096,4096]
    const float* bb = (const float*)d_in[2];   // [4096]
    const float* Wr = (const float*)d_in[3];   // [8,4096]
    const float* A  = (const float*)d_in[4];   // [8,16,4096] == [ERD, DIN]
    const float* B  = (const float*)d_in[5];   // [8,4096,16]
    float* out = (float*)d_out;

    void *pX, *pW, *pA;
    cudaGetSymbolAddress(&pX, g_X);
    cudaGetSymbolAddress(&pW, g_W);
    cudaGetSymbolAddress(&pA, g_A);

    const int smem_main = 1024 + 3 * (256 * 128 + 16384);   // 148480
    const int smem_lora = 1024 + 3 * (64 * 128 + 16384);    //  74752
    cudaFuncSetAttribute(gemm_mma<8, 0>,
        cudaFuncAttributeMaxDynamicSharedMemorySize, smem_main);
    cudaFuncSetAttribute(gemm_mma<2, 1>,
        cudaFuncAttributeMaxDynamicSharedMemorySize, smem_lora);

    router_kernel<<<TT / 8, 256>>>(x, Wr);
    cvt_h<<<TT * DIN / 8 / 256, 256>>>(x, (__half*)pX, KAUG);
    cvt_h<<<ERD * DIN / 8 / 256, 256>>>(A, (__half*)pA, DIN);
    cvt_h<<<DOUT * DIN / 8 / 256, 256>>>(Wb, (__half*)pW, KAUG);
    bt_cvt<<<DOUT * ERD / 256, 256>>>(B);

    // LoRA down-projection: G = softmax-weighted (x @ A^T) -> augmented X cols
    gemm_mma<2, 1><<<dim3(1, TT / 64), 128, smem_lora>>>(
        (const __half*)pX, KAUG,
        (const __half*)pA, DIN,
        DIN / 64, nullptr, nullptr);

    // Main fused GEMM: out = [x|G] @ [W|Bt]^T + bias
    gemm_mma<8, 0><<<dim3(DOUT / 128, TT / 256), 512, smem_main>>>(
        (const __half*)pX, KAUG,
        (const __half*)pW, KAUG,
        KAUG / 64, bb, out);
}